// round 1
// baseline (speedup 1.0000x reference)
#include <cuda_runtime.h>
#include <math.h>

// Problem constants
#define NB     2
#define SS     1024
#define NTOK   2048        // NB*SS
#define DD     1024
#define HH     2048
#define EE     8
#define KTOP   2

// ---- device scratch (static, allocation-free) ----
__device__ float g_xnorm[(size_t)NTOK * DD];              // 8 MB
__device__ int   g_counts[EE];
__device__ int   g_rowid[EE * NTOK];                      // rowid = token*2 + slot
__device__ float g_assign_w[NTOK * KTOP];
__device__ float g_hidden[(size_t)NTOK * KTOP * HH];      // 32 MB
__device__ float g_y[(size_t)NTOK * KTOP * DD];           // 16 MB

__global__ void zero_counts_kernel() {
    if (threadIdx.x < EE) g_counts[threadIdx.x] = 0;
}

// ---------------------------------------------------------------------------
// Kernel A: RMSNorm + router (one block per token, 256 threads)
// ---------------------------------------------------------------------------
__global__ void __launch_bounds__(256) norm_router_kernel(
    const float* __restrict__ x, const float* __restrict__ gvec,
    const float* __restrict__ gate_w)
{
    const int t   = blockIdx.x;
    const int tid = threadIdx.x;
    __shared__ float sh[DD];
    __shared__ float red[8];
    __shared__ float logit[EE];

    const float4 v = ((const float4*)(x + (size_t)t * DD))[tid];  // 256 f4 = 1024
    float ss = v.x*v.x + v.y*v.y + v.z*v.z + v.w*v.w;
    #pragma unroll
    for (int o = 16; o; o >>= 1) ss += __shfl_xor_sync(0xffffffffu, ss, o);
    if ((tid & 31) == 0) red[tid >> 5] = ss;
    __syncthreads();
    if (tid < 8) {
        float s = red[tid];
        #pragma unroll
        for (int o = 4; o; o >>= 1) s += __shfl_xor_sync(0xffu, s, o);
        if (tid == 0) red[0] = s;
    }
    __syncthreads();
    const float rinv = rsqrtf(red[0] * (1.0f / DD) + 1e-5f);
    const float4 gv = ((const float4*)gvec)[tid];
    float4 xn;
    xn.x = v.x * rinv * gv.x;
    xn.y = v.y * rinv * gv.y;
    xn.z = v.z * rinv * gv.z;
    xn.w = v.w * rinv * gv.w;
    ((float4*)sh)[tid] = xn;
    ((float4*)(g_xnorm + (size_t)t * DD))[tid] = xn;
    __syncthreads();

    // 8 warps -> 8 expert logits
    const int w = tid >> 5, lane = tid & 31;
    float acc = 0.f;
    const float* gw = gate_w + (size_t)w * DD;
    for (int d = lane; d < DD; d += 32) acc += sh[d] * gw[d];
    #pragma unroll
    for (int o = 16; o; o >>= 1) acc += __shfl_xor_sync(0xffffffffu, acc, o);
    if (lane == 0) logit[w] = acc;
    __syncthreads();

    if (tid == 0) {
        float mx = logit[0];
        #pragma unroll
        for (int e = 1; e < EE; e++) mx = fmaxf(mx, logit[e]);
        float p[EE]; float Z = 0.f;
        #pragma unroll
        for (int e = 0; e < EE; e++) { p[e] = expf(logit[e] - mx); Z += p[e]; }
        const float iz = 1.f / Z;
        #pragma unroll
        for (int e = 0; e < EE; e++) p[e] *= iz;
        int i0 = 0;
        #pragma unroll
        for (int e = 1; e < EE; e++) if (p[e] > p[i0]) i0 = e;
        int i1 = (i0 == 0) ? 1 : 0;
        #pragma unroll
        for (int e = 0; e < EE; e++) if (e != i1 && e != i0 && p[e] > p[i1]) i1 = e;
        const float denom = p[i0] + p[i1] + 1e-10f;
        const float w0 = p[i0] / denom, w1 = p[i1] / denom;
        int pos0 = atomicAdd(&g_counts[i0], 1);
        g_rowid[i0 * NTOK + pos0] = t * 2 + 0;
        g_assign_w[t * 2 + 0] = w0;
        int pos1 = atomicAdd(&g_counts[i1], 1);
        g_rowid[i1 * NTOK + pos1] = t * 2 + 1;
        g_assign_w[t * 2 + 1] = w1;
    }
}

// ---------------------------------------------------------------------------
// Kernel B: grouped dual GEMM: hidden = silu(Xg @ w1[e]) * (Xg @ w2[e])
// Tile 128(M) x 64(N), K-step 16, 256 threads, 8x4 microtile per matrix.
// grid = (HH/64, NTOK/128, EE)
// ---------------------------------------------------------------------------
#define TM 128
#define TN 64
#define TKD 16

__device__ __forceinline__ float silu_f(float v) {
    return v / (1.0f + expf(-v));
}

__global__ void __launch_bounds__(256, 2) gemm1_kernel(
    const float* __restrict__ w1, const float* __restrict__ w2)
{
    const int e  = blockIdx.z;
    const int mt = blockIdx.y;
    const int nt = blockIdx.x;
    const int ne = g_counts[e];
    if (mt * TM >= ne) return;

    __shared__ float As[TKD][TM];
    __shared__ float Bs1[TKD][TN];
    __shared__ float Bs2[TKD][TN];
    __shared__ int rows[TM];

    const int tid = threadIdx.x;
    if (tid < TM) {
        int m = mt * TM + tid;
        rows[tid] = (m < ne) ? g_rowid[e * NTOK + m] : -1;
    }
    __syncthreads();

    const int tm = (tid >> 4) << 3;   // 0..120 step 8
    const int tn = (tid & 15) << 2;   // 0..60  step 4
    float acc1[8][4] = {};
    float acc2[8][4] = {};

    // load-index precompute
    const int lm   = tid & 127;       // A row
    const int half = tid >> 7;        // 0/1
    const int bk   = tid >> 4;        // B row (k)
    const int bn   = (tid & 15) << 2; // B col
    const float* w1e = w1 + (size_t)e * DD * HH;
    const float* w2e = w2 + (size_t)e * DD * HH;
    const int h0 = nt * TN;
    const int rA = rows[lm];
    const float* arow = (rA >= 0) ? (g_xnorm + (size_t)(rA >> 1) * DD) : g_xnorm;

    for (int k0 = 0; k0 < DD; k0 += TKD) {
        #pragma unroll
        for (int j = 0; j < 2; j++) {
            const int kb = half * 4 + j * 8;
            float4 av = make_float4(0.f, 0.f, 0.f, 0.f);
            if (rA >= 0) av = *(const float4*)(arow + k0 + kb);
            As[kb + 0][lm] = av.x;
            As[kb + 1][lm] = av.y;
            As[kb + 2][lm] = av.z;
            As[kb + 3][lm] = av.w;
        }
        *(float4*)&Bs1[bk][bn] = *(const float4*)(w1e + (size_t)(k0 + bk) * HH + h0 + bn);
        *(float4*)&Bs2[bk][bn] = *(const float4*)(w2e + (size_t)(k0 + bk) * HH + h0 + bn);
        __syncthreads();

        #pragma unroll
        for (int kk = 0; kk < TKD; kk++) {
            const float4 a0 = *(const float4*)&As[kk][tm];
            const float4 a1 = *(const float4*)&As[kk][tm + 4];
            const float4 b1 = *(const float4*)&Bs1[kk][tn];
            const float4 b2 = *(const float4*)&Bs2[kk][tn];
            const float av[8]  = {a0.x, a0.y, a0.z, a0.w, a1.x, a1.y, a1.z, a1.w};
            const float b1v[4] = {b1.x, b1.y, b1.z, b1.w};
            const float b2v[4] = {b2.x, b2.y, b2.z, b2.w};
            #pragma unroll
            for (int i = 0; i < 8; i++) {
                #pragma unroll
                for (int j = 0; j < 4; j++) {
                    acc1[i][j] += av[i] * b1v[j];
                    acc2[i][j] += av[i] * b2v[j];
                }
            }
        }
        __syncthreads();
    }

    #pragma unroll
    for (int i = 0; i < 8; i++) {
        const int r = rows[tm + i];
        if (r < 0) continue;
        float4 o;
        o.x = silu_f(acc1[i][0]) * acc2[i][0];
        o.y = silu_f(acc1[i][1]) * acc2[i][1];
        o.z = silu_f(acc1[i][2]) * acc2[i][2];
        o.w = silu_f(acc1[i][3]) * acc2[i][3];
        *(float4*)(g_hidden + (size_t)r * HH + h0 + tn) = o;
    }
}

// ---------------------------------------------------------------------------
// Kernel C: grouped GEMM: y = hidden @ w3[e]   (K-dim = HH)
// Tile 128 x 64, K-step 16, 256 threads, 8x4 microtile.
// grid = (DD/64, NTOK/128, EE)
// ---------------------------------------------------------------------------
__global__ void __launch_bounds__(256, 2) gemm2_kernel(const float* __restrict__ w3)
{
    const int e  = blockIdx.z;
    const int mt = blockIdx.y;
    const int nt = blockIdx.x;
    const int ne = g_counts[e];
    if (mt * TM >= ne) return;

    __shared__ float As[TKD][TM];
    __shared__ float Bs[TKD][TN];
    __shared__ int rows[TM];

    const int tid = threadIdx.x;
    if (tid < TM) {
        int m = mt * TM + tid;
        rows[tid] = (m < ne) ? g_rowid[e * NTOK + m] : -1;
    }
    __syncthreads();

    const int tm = (tid >> 4) << 3;
    const int tn = (tid & 15) << 2;
    float acc[8][4] = {};

    const int lm   = tid & 127;
    const int half = tid >> 7;
    const int bk   = tid >> 4;
    const int bn   = (tid & 15) << 2;
    const float* w3e = w3 + (size_t)e * HH * DD;
    const int d0 = nt * TN;
    const int rA = rows[lm];
    const float* arow = (rA >= 0) ? (g_hidden + (size_t)rA * HH) : g_hidden;

    for (int k0 = 0; k0 < HH; k0 += TKD) {
        #pragma unroll
        for (int j = 0; j < 2; j++) {
            const int kb = half * 4 + j * 8;
            float4 av = make_float4(0.f, 0.f, 0.f, 0.f);
            if (rA >= 0) av = *(const float4*)(arow + k0 + kb);
            As[kb + 0][lm] = av.x;
            As[kb + 1][lm] = av.y;
            As[kb + 2][lm] = av.z;
            As[kb + 3][lm] = av.w;
        }
        *(float4*)&Bs[bk][bn] = *(const float4*)(w3e + (size_t)(k0 + bk) * DD + d0 + bn);
        __syncthreads();

        #pragma unroll
        for (int kk = 0; kk < TKD; kk++) {
            const float4 a0 = *(const float4*)&As[kk][tm];
            const float4 a1 = *(const float4*)&As[kk][tm + 4];
            const float4 b  = *(const float4*)&Bs[kk][tn];
            const float av[8] = {a0.x, a0.y, a0.z, a0.w, a1.x, a1.y, a1.z, a1.w};
            const float bv[4] = {b.x, b.y, b.z, b.w};
            #pragma unroll
            for (int i = 0; i < 8; i++) {
                #pragma unroll
                for (int j = 0; j < 4; j++)
                    acc[i][j] += av[i] * bv[j];
            }
        }
        __syncthreads();
    }

    #pragma unroll
    for (int i = 0; i < 8; i++) {
        const int r = rows[tm + i];
        if (r < 0) continue;
        float4 o = make_float4(acc[i][0], acc[i][1], acc[i][2], acc[i][3]);
        *(float4*)(g_y + (size_t)r * DD + d0 + tn) = o;
    }
}

// ---------------------------------------------------------------------------
// Kernel D: deterministic 2-slot combine: out[t] = w0*y[2t] + w1*y[2t+1]
// ---------------------------------------------------------------------------
__global__ void __launch_bounds__(256) combine_kernel(float* __restrict__ out)
{
    const int t   = blockIdx.x;
    const int tid = threadIdx.x;   // 256 -> DD/4 float4s
    const float w0 = g_assign_w[2 * t + 0];
    const float w1 = g_assign_w[2 * t + 1];
    const float4 a = ((const float4*)(g_y + (size_t)(2 * t + 0) * DD))[tid];
    const float4 b = ((const float4*)(g_y + (size_t)(2 * t + 1) * DD))[tid];
    float4 o;
    o.x = w0 * a.x + w1 * b.x;
    o.y = w0 * a.y + w1 * b.y;
    o.z = w0 * a.z + w1 * b.z;
    o.w = w0 * a.w + w1 * b.w;
    ((float4*)(out + (size_t)t * DD))[tid] = o;
}

// ---------------------------------------------------------------------------
extern "C" void kernel_launch(void* const* d_in, const int* in_sizes, int n_in,
                              void* d_out, int out_size)
{
    const float* x      = (const float*)d_in[0];
    const float* gvec   = (const float*)d_in[1];
    const float* gate_w = (const float*)d_in[2];
    const float* w1     = (const float*)d_in[3];
    const float* w2     = (const float*)d_in[4];
    const float* w3     = (const float*)d_in[5];
    float* out = (float*)d_out;

    zero_counts_kernel<<<1, 32>>>();
    norm_router_kernel<<<NTOK, 256>>>(x, gvec, gate_w);
    gemm1_kernel<<<dim3(HH / TN, NTOK / TM, EE), 256>>>(w1, w2);
    gemm2_kernel<<<dim3(DD / TN, NTOK / TM, EE), 256>>>(w3);
    combine_kernel<<<NTOK, 256>>>(out);
}

// round 6
// speedup vs baseline: 1.1019x; 1.1019x over previous
#include <cuda_runtime.h>
#include <math.h>
#include <stdint.h>

// Problem constants
#define NTOK   2048
#define DD     1024
#define HH     2048
#define EE     8
#define NROWS  4096        // NTOK * topk(2) slot-rows

// ---------------------------------------------------------------------------
// Device scratch (static, allocation-free) — same footprint family as R1 (passed)
// ---------------------------------------------------------------------------
__device__ float g_xnorm[(size_t)NTOK * DD];              // 8 MB
__device__ float g_hidden[(size_t)NROWS * HH];            // 32 MB
__device__ float g_y[(size_t)NROWS * DD];                 // 16 MB
__device__ int   g_counts[EE];
__device__ int   g_rowid[EE * NROWS];
__device__ float g_assign_w[NROWS];

__global__ void zero_counts_kernel() {
    if (threadIdx.x < EE) g_counts[threadIdx.x] = 0;
}

__device__ __forceinline__ float silu_f(float v) {
    return v / (1.0f + expf(-v));
}

// ---------------------------------------------------------------------------
// Kernel A: RMSNorm + router (verbatim from R1 — proven)
// ---------------------------------------------------------------------------
__global__ void __launch_bounds__(256) norm_router_kernel(
    const float* __restrict__ x, const float* __restrict__ gvec,
    const float* __restrict__ gate_w)
{
    const int t   = blockIdx.x;
    const int tid = threadIdx.x;
    __shared__ float sh[DD];
    __shared__ float red[8];
    __shared__ float logit[EE];

    const float4 v = ((const float4*)(x + (size_t)t * DD))[tid];
    float ss = v.x*v.x + v.y*v.y + v.z*v.z + v.w*v.w;
    #pragma unroll
    for (int o = 16; o; o >>= 1) ss += __shfl_xor_sync(0xffffffffu, ss, o);
    if ((tid & 31) == 0) red[tid >> 5] = ss;
    __syncthreads();
    if (tid < 8) {
        float s = red[tid];
        #pragma unroll
        for (int o = 4; o; o >>= 1) s += __shfl_xor_sync(0xffu, s, o);
        if (tid == 0) red[0] = s;
    }
    __syncthreads();
    const float rinv = rsqrtf(red[0] * (1.0f / DD) + 1e-5f);
    const float4 gv = ((const float4*)gvec)[tid];
    float4 xn;
    xn.x = v.x * rinv * gv.x;
    xn.y = v.y * rinv * gv.y;
    xn.z = v.z * rinv * gv.z;
    xn.w = v.w * rinv * gv.w;
    ((float4*)sh)[tid] = xn;
    ((float4*)(g_xnorm + (size_t)t * DD))[tid] = xn;
    __syncthreads();

    const int w = tid >> 5, lane = tid & 31;
    float acc = 0.f;
    const float* gw = gate_w + (size_t)w * DD;
    for (int d = lane; d < DD; d += 32) acc += sh[d] * gw[d];
    #pragma unroll
    for (int o = 16; o; o >>= 1) acc += __shfl_xor_sync(0xffffffffu, acc, o);
    if (lane == 0) logit[w] = acc;
    __syncthreads();

    if (tid == 0) {
        float mx = logit[0];
        #pragma unroll
        for (int e = 1; e < EE; e++) mx = fmaxf(mx, logit[e]);
        float p[EE]; float Z = 0.f;
        #pragma unroll
        for (int e = 0; e < EE; e++) { p[e] = expf(logit[e] - mx); Z += p[e]; }
        const float iz = 1.f / Z;
        #pragma unroll
        for (int e = 0; e < EE; e++) p[e] *= iz;
        int i0 = 0;
        #pragma unroll
        for (int e = 1; e < EE; e++) if (p[e] > p[i0]) i0 = e;
        int i1 = (i0 == 0) ? 1 : 0;
        #pragma unroll
        for (int e = 0; e < EE; e++) if (e != i1 && e != i0 && p[e] > p[i1]) i1 = e;
        const float denom = p[i0] + p[i1] + 1e-10f;
        int pos0 = atomicAdd(&g_counts[i0], 1);
        g_rowid[i0 * NROWS + pos0] = t * 2 + 0;
        g_assign_w[t * 2 + 0] = p[i0] / denom;
        int pos1 = atomicAdd(&g_counts[i1], 1);
        g_rowid[i1 * NROWS + pos1] = t * 2 + 1;
        g_assign_w[t * 2 + 1] = p[i1] / denom;
    }
}

// ---------------------------------------------------------------------------
// GEMM1: dual GEMM hidden = silu(Xg@w1) * (Xg@w2)
// CTA tile 128M x 64N (per B), 256 threads, microtile 8Mx4N per B (4+4 split rows).
// K-step 16, double-buffered smem, ONE barrier per step.
// Smem: As[2][16][128] 16KB, B1s/B2s[2][16][64] 8KB each = 32KB.
// grid = (HH/64, NROWS/128, EE)
// ---------------------------------------------------------------------------
__global__ void __launch_bounds__(256) gemm1_kernel(
    const float* __restrict__ w1, const float* __restrict__ w2)
{
    const int e = blockIdx.z, mtb = blockIdx.y, ntb = blockIdx.x;
    const int ne = g_counts[e];
    if (mtb * 128 >= ne) return;

    __shared__ float As[2][16][128];
    __shared__ float B1s[2][16][64];
    __shared__ float B2s[2][16][64];
    __shared__ int rows[128];

    const int tid = threadIdx.x;
    if (tid < 128) {
        const int m = mtb * 128 + tid;
        rows[tid] = (m < ne) ? g_rowid[e * NROWS + m] : -1;
    }
    __syncthreads();

    // ---- loader setup ----
    const int arow = tid >> 1, ahalf = tid & 1;     // 2 threads per A row, 8 k each
    const int rA = rows[arow];
    const float* aptr = (rA >= 0) ? (g_xnorm + (size_t)(rA >> 1) * DD) : g_xnorm;
    const int bty = tid >> 4, btc = tid & 15;       // B: 16 k-rows x 16 float4 chunks
    const float* b1p = w1 + (size_t)e * DD * HH + ntb * 64;
    const float* b2p = w2 + (size_t)e * DD * HH + ntb * 64;

    float4 ra0, ra1, rb1, rb2;
    auto ldg = [&](int i) {
        const int k0 = i * 16;
        if (rA >= 0) {
            ra0 = *(const float4*)(aptr + k0 + ahalf * 8);
            ra1 = *(const float4*)(aptr + k0 + ahalf * 8 + 4);
        } else {
            ra0 = make_float4(0.f, 0.f, 0.f, 0.f);
            ra1 = ra0;
        }
        rb1 = *(const float4*)(b1p + (size_t)(k0 + bty) * HH + btc * 4);
        rb2 = *(const float4*)(b2p + (size_t)(k0 + bty) * HH + btc * 4);
    };
    auto sts = [&](int buf) {
        const float av[8] = {ra0.x, ra0.y, ra0.z, ra0.w, ra1.x, ra1.y, ra1.z, ra1.w};
        #pragma unroll
        for (int j = 0; j < 8; j++) As[buf][ahalf * 8 + j][arow] = av[j];
        *(float4*)&B1s[buf][bty][btc * 4] = rb1;
        *(float4*)&B2s[buf][bty][btc * 4] = rb2;
    };
    ldg(0); sts(0); __syncthreads();

    // ---- compute setup: thread (ty,tx): rows {ty*4..+3, ty*4+64..+67}, cols tx*4..+3
    const int ty = tid >> 4, tx = tid & 15;
    const int m0 = ty * 4, n0 = tx * 4;
    float acc1[8][4] = {};
    float acc2[8][4] = {};

    for (int i = 0; i < 64; i++) {
        if (i + 1 < 64) ldg(i + 1);
        const int buf = i & 1;
        #pragma unroll
        for (int kk = 0; kk < 16; kk++) {
            const float4 a0 = *(const float4*)&As[buf][kk][m0];
            const float4 a1 = *(const float4*)&As[buf][kk][m0 + 64];
            const float4 b1 = *(const float4*)&B1s[buf][kk][n0];
            const float4 b2 = *(const float4*)&B2s[buf][kk][n0];
            const float am[8]  = {a0.x, a0.y, a0.z, a0.w, a1.x, a1.y, a1.z, a1.w};
            const float bv1[4] = {b1.x, b1.y, b1.z, b1.w};
            const float bv2[4] = {b2.x, b2.y, b2.z, b2.w};
            #pragma unroll
            for (int m = 0; m < 8; m++) {
                #pragma unroll
                for (int n = 0; n < 4; n++) {
                    acc1[m][n] += am[m] * bv1[n];
                    acc2[m][n] += am[m] * bv2[n];
                }
            }
        }
        if (i + 1 < 64) sts((i + 1) & 1);
        __syncthreads();
    }

    // ---- epilogue: silu(h1)*h2 -> g_hidden ----
    const int h0 = ntb * 64;
    #pragma unroll
    for (int half = 0; half < 2; half++) {
        #pragma unroll
        for (int q = 0; q < 4; q++) {
            const int ml = m0 + half * 64 + q;
            const int r = rows[ml];
            if (r < 0) continue;
            const int idx = half * 4 + q;
            float4 o;
            o.x = silu_f(acc1[idx][0]) * acc2[idx][0];
            o.y = silu_f(acc1[idx][1]) * acc2[idx][1];
            o.z = silu_f(acc1[idx][2]) * acc2[idx][2];
            o.w = silu_f(acc1[idx][3]) * acc2[idx][3];
            *(float4*)(g_hidden + (size_t)r * HH + h0 + n0) = o;
        }
    }
}

// ---------------------------------------------------------------------------
// GEMM2: y = hidden @ w3[e]
// CTA tile 128M x 128N, 256 threads, microtile 8x8 (4+4 split rows AND cols).
// K-step 16, double-buffered, one barrier per step.
// Smem: As[2][16][128] 16KB + Bs[2][16][128] 16KB = 32KB.
// grid = (DD/128, NROWS/128, EE)
// ---------------------------------------------------------------------------
__global__ void __launch_bounds__(256) gemm2_kernel(const float* __restrict__ w3)
{
    const int e = blockIdx.z, mtb = blockIdx.y, ntb = blockIdx.x;
    const int ne = g_counts[e];
    if (mtb * 128 >= ne) return;

    __shared__ float As[2][16][128];
    __shared__ float Bs[2][16][128];
    __shared__ int rows[128];

    const int tid = threadIdx.x;
    if (tid < 128) {
        const int m = mtb * 128 + tid;
        rows[tid] = (m < ne) ? g_rowid[e * NROWS + m] : -1;
    }
    __syncthreads();

    const int arow = tid >> 1, ahalf = tid & 1;
    const int rA = rows[arow];
    const float* aptr = (rA >= 0) ? (g_hidden + (size_t)rA * HH) : g_hidden;
    const int bty = tid >> 4, btc = tid & 15;
    const float* bp = w3 + (size_t)e * HH * DD + ntb * 128;

    float4 ra0, ra1, rb0, rb1;
    auto ldg = [&](int i) {
        const int k0 = i * 16;
        if (rA >= 0) {
            ra0 = *(const float4*)(aptr + k0 + ahalf * 8);
            ra1 = *(const float4*)(aptr + k0 + ahalf * 8 + 4);
        } else {
            ra0 = make_float4(0.f, 0.f, 0.f, 0.f);
            ra1 = ra0;
        }
        const float* brow = bp + (size_t)(k0 + bty) * DD;
        rb0 = *(const float4*)(brow + btc * 4);
        rb1 = *(const float4*)(brow + btc * 4 + 64);
    };
    auto sts = [&](int buf) {
        const float av[8] = {ra0.x, ra0.y, ra0.z, ra0.w, ra1.x, ra1.y, ra1.z, ra1.w};
        #pragma unroll
        for (int j = 0; j < 8; j++) As[buf][ahalf * 8 + j][arow] = av[j];
        *(float4*)&Bs[buf][bty][btc * 4]      = rb0;
        *(float4*)&Bs[buf][bty][btc * 4 + 64] = rb1;
    };
    ldg(0); sts(0); __syncthreads();

    const int ty = tid >> 4, tx = tid & 15;
    const int m0 = ty * 4, n0 = tx * 4;
    float acc[8][8] = {};

    for (int i = 0; i < 128; i++) {
        if (i + 1 < 128) ldg(i + 1);
        const int buf = i & 1;
        #pragma unroll
        for (int kk = 0; kk < 16; kk++) {
            const float4 a0 = *(const float4*)&As[buf][kk][m0];
            const float4 a1 = *(const float4*)&As[buf][kk][m0 + 64];
            const float4 b0 = *(const float4*)&Bs[buf][kk][n0];
            const float4 b1 = *(const float4*)&Bs[buf][kk][n0 + 64];
            const float am[8] = {a0.x, a0.y, a0.z, a0.w, a1.x, a1.y, a1.z, a1.w};
            const float bv[8] = {b0.x, b0.y, b0.z, b0.w, b1.x, b1.y, b1.z, b1.w};
            #pragma unroll
            for (int m = 0; m < 8; m++) {
                #pragma unroll
                for (int n = 0; n < 8; n++)
                    acc[m][n] += am[m] * bv[n];
            }
        }
        if (i + 1 < 128) sts((i + 1) & 1);
        __syncthreads();
    }

    const int d0 = ntb * 128;
    #pragma unroll
    for (int half = 0; half < 2; half++) {
        #pragma unroll
        for (int q = 0; q < 4; q++) {
            const int ml = m0 + half * 64 + q;
            const int r = rows[ml];
            if (r < 0) continue;
            const int idx = half * 4 + q;
            float* yrow = g_y + (size_t)r * DD + d0;
            float4 o0 = make_float4(acc[idx][0], acc[idx][1], acc[idx][2], acc[idx][3]);
            float4 o1 = make_float4(acc[idx][4], acc[idx][5], acc[idx][6], acc[idx][7]);
            *(float4*)(yrow + n0)      = o0;
            *(float4*)(yrow + n0 + 64) = o1;
        }
    }
}

// ---------------------------------------------------------------------------
// Kernel D: combine out[t] = w0*y[2t] + w1*y[2t+1]  (verbatim from R1)
// ---------------------------------------------------------------------------
__global__ void __launch_bounds__(256) combine_kernel(float* __restrict__ out)
{
    const int t   = blockIdx.x;
    const int tid = threadIdx.x;
    const float w0 = g_assign_w[2 * t + 0];
    const float w1 = g_assign_w[2 * t + 1];
    const float4 a = ((const float4*)(g_y + (size_t)(2 * t + 0) * DD))[tid];
    const float4 b = ((const float4*)(g_y + (size_t)(2 * t + 1) * DD))[tid];
    float4 o;
    o.x = w0 * a.x + w1 * b.x;
    o.y = w0 * a.y + w1 * b.y;
    o.z = w0 * a.z + w1 * b.z;
    o.w = w0 * a.w + w1 * b.w;
    ((float4*)(out + (size_t)t * DD))[tid] = o;
}

// ---------------------------------------------------------------------------
extern "C" void kernel_launch(void* const* d_in, const int* in_sizes, int n_in,
                              void* d_out, int out_size)
{
    const float* x      = (const float*)d_in[0];
    const float* gvec   = (const float*)d_in[1];
    const float* gate_w = (const float*)d_in[2];
    const float* w1     = (const float*)d_in[3];
    const float* w2     = (const float*)d_in[4];
    const float* w3     = (const float*)d_in[5];
    float* out = (float*)d_out;

    zero_counts_kernel<<<1, 32>>>();
    norm_router_kernel<<<NTOK, 256>>>(x, gvec, gate_w);
    gemm1_kernel<<<dim3(HH / 64, NROWS / 128, EE), 256>>>(w1, w2);
    gemm2_kernel<<<dim3(DD / 128, NROWS / 128, EE), 256>>>(w3);
    combine_kernel<<<NTOK, 256>>>(out);
}